// round 10
// baseline (speedup 1.0000x reference)
#include <cuda_runtime.h>

// Problem dimensions (fixed by the reference)
#define TT_  4096   // sequence length T
#define EE_  256    // embed dim E
#define HH_  256    // per-direction hidden Hh
#define GG_  1024   // 4*Hh gate rows
#define KK_  32     // tags K
#define HC_  512    // concat hidden H

// ---------------- device scratch (no mallocs allowed) ----------------
__device__ float g_pre[2][TT_][GG_];   // input projections + biases, per direction (32 MB)
__device__ float g_h[TT_][HC_];        // concat hidden states (8 MB)
__device__ float g_feats[TT_][KK_];    // emission scores (512 KB)

// ---------------- packed fp32x2 helpers (SASS FFMA2) ----------------
__device__ __forceinline__ unsigned long long ffma2_(unsigned long long a,
                                                     unsigned long long b,
                                                     unsigned long long c) {
    unsigned long long d;
    asm("fma.rn.f32x2 %0, %1, %2, %3;" : "=l"(d) : "l"(a), "l"(b), "l"(c));
    return d;
}
__device__ __forceinline__ unsigned long long pack2_(float x) {
    unsigned long long d;
    asm("mov.b64 %0, {%1, %1};" : "=l"(d) : "f"(x));
    return d;
}
__device__ __forceinline__ float2 unpack2_(unsigned long long v) {
    float2 r;
    asm("mov.b64 {%0, %1}, %2;" : "=f"(r.x), "=f"(r.y) : "l"(v));
    return r;
}

// =====================================================================
// Phase 1: fused embedding gather + input projection GEMM (f32x2)
// =====================================================================
__global__ void __launch_bounds__(256) pre_gemm_kernel(
    const int* __restrict__ sent, const float* __restrict__ embed,
    const float* __restrict__ WihF, const float* __restrict__ bihF, const float* __restrict__ bhhF,
    const float* __restrict__ WihB, const float* __restrict__ bihB, const float* __restrict__ bhhB)
{
    const int dir = blockIdx.z;
    const float* __restrict__ Wih = dir ? WihB : WihF;
    const float* __restrict__ bih = dir ? bihB : bihF;
    const float* __restrict__ bhh = dir ? bhhB : bhhF;

    const int t0 = blockIdx.y * 64;
    const int j0 = blockIdx.x * 64;
    const int tid = threadIdx.x;

    __shared__ __align__(16) float As[32][68];
    __shared__ __align__(16) float Bs[32][68];
    __shared__ int ssent[64];

    if (tid < 64) ssent[tid] = sent[t0 + tid];
    __syncthreads();

    const int tl = tid >> 2;
    const int kq = (tid & 3) * 8;
    const int tm = tid & 15;
    const int tn = tid >> 4;

    unsigned long long acc2[4][2];
#pragma unroll
    for (int a = 0; a < 4; a++) { acc2[a][0] = 0ull; acc2[a][1] = 0ull; }

    for (int k0 = 0; k0 < EE_; k0 += 32) {
        const float4* ar = reinterpret_cast<const float4*>(embed + (size_t)ssent[tl] * EE_ + k0 + kq);
        float4 a0 = ar[0], a1 = ar[1];
        const float4* br = reinterpret_cast<const float4*>(Wih + (size_t)(j0 + tl) * EE_ + k0 + kq);
        float4 b0 = br[0], b1 = br[1];
        __syncthreads();
        As[kq + 0][tl] = a0.x; As[kq + 1][tl] = a0.y; As[kq + 2][tl] = a0.z; As[kq + 3][tl] = a0.w;
        As[kq + 4][tl] = a1.x; As[kq + 5][tl] = a1.y; As[kq + 6][tl] = a1.z; As[kq + 7][tl] = a1.w;
        Bs[kq + 0][tl] = b0.x; Bs[kq + 1][tl] = b0.y; Bs[kq + 2][tl] = b0.z; Bs[kq + 3][tl] = b0.w;
        Bs[kq + 4][tl] = b1.x; Bs[kq + 5][tl] = b1.y; Bs[kq + 6][tl] = b1.z; Bs[kq + 7][tl] = b1.w;
        __syncthreads();
#pragma unroll
        for (int kk = 0; kk < 32; kk++) {
            float4 av = *reinterpret_cast<const float4*>(&As[kk][tm * 4]);
            ulonglong2 bv = *reinterpret_cast<const ulonglong2*>(&Bs[kk][tn * 4]);
            unsigned long long sa0 = pack2_(av.x), sa1 = pack2_(av.y);
            unsigned long long sa2 = pack2_(av.z), sa3 = pack2_(av.w);
            acc2[0][0] = ffma2_(sa0, bv.x, acc2[0][0]); acc2[0][1] = ffma2_(sa0, bv.y, acc2[0][1]);
            acc2[1][0] = ffma2_(sa1, bv.x, acc2[1][0]); acc2[1][1] = ffma2_(sa1, bv.y, acc2[1][1]);
            acc2[2][0] = ffma2_(sa2, bv.x, acc2[2][0]); acc2[2][1] = ffma2_(sa2, bv.y, acc2[2][1]);
            acc2[3][0] = ffma2_(sa3, bv.x, acc2[3][0]); acc2[3][1] = ffma2_(sa3, bv.y, acc2[3][1]);
        }
    }

    float bias[4];
#pragma unroll
    for (int b = 0; b < 4; b++) bias[b] = bih[j0 + tn * 4 + b] + bhh[j0 + tn * 4 + b];

#pragma unroll
    for (int a = 0; a < 4; a++) {
        float2 p0 = unpack2_(acc2[a][0]);
        float2 p1 = unpack2_(acc2[a][1]);
        float4 v;
        v.x = p0.x + bias[0]; v.y = p0.y + bias[1];
        v.z = p1.x + bias[2]; v.w = p1.y + bias[3];
        *reinterpret_cast<float4*>(&g_pre[dir][t0 + tm * 4 + a][j0 + tn * 4]) = v;
    }
}

// ---------------- recurrence helpers ----------------
__device__ __forceinline__ float sigm_(float x) {
    return __fdividef(1.f, 1.f + __expf(-x));     // rcp.approx path
}
__device__ __forceinline__ float tanh_(float x) {
    return __fdividef(2.f, 1.f + __expf(-2.f * x)) - 1.f;
}
__device__ __forceinline__ void cluster_sync_() {
    asm volatile("barrier.cluster.arrive.aligned;" ::: "memory");
    asm volatile("barrier.cluster.wait.aligned;" ::: "memory");
}
__device__ __forceinline__ void mbar_wait_cluster_(unsigned mbar, unsigned parity) {
    unsigned done;
    asm volatile(
        "{\n\t.reg .pred p;\n\t"
        "mbarrier.try_wait.parity.acquire.cluster.shared::cta.b64 p, [%1], %2, 0x989680;\n\t"
        "selp.b32 %0, 1, 0, p;\n\t}"
        : "=r"(done) : "r"(mbar), "r"(parity) : "memory");
    while (!done) {
        asm volatile(
            "{\n\t.reg .pred p;\n\t"
            "mbarrier.try_wait.parity.acquire.cluster.shared::cta.b64 p, [%1], %2, 0x989680;\n\t"
            "selp.b32 %0, 1, 0, p;\n\t}"
            : "=r"(done) : "r"(mbar), "r"(parity) : "memory");
    }
}

// =====================================================================
// Phase 2: BiLSTM recurrence. 2 clusters of 8 CTAs (dir = blockIdx.x>>3).
// tid = u*8 + sub, sub = g*2 + half. Weights in registers as f32x2 pairs.
// Send: ONE st.async per thread (data + destination-barrier tx-update in a
// single fabric transaction — no source-side release drain). Barriers are
// expect_tx-based: count=1, 1024 B (= 256 stores x 4B) per phase. tid0
// re-arms a barrier right after passing its wait (next use is 2 steps out,
// so expect_tx always precedes any complete_tx of that phase).
// =====================================================================
__global__ void __cluster_dims__(8, 1, 1) __launch_bounds__(256, 1) lstm_rec_kernel(
    const float* __restrict__ WhhF, const float* __restrict__ WhhB,
    const float* __restrict__ h0, const float* __restrict__ c0)
{
    __shared__ __align__(16) float hbuf[2][HH_];     // assembled h (all 8 chunks)
    __shared__ __align__(8) unsigned long long mbar[2];

    unsigned rank;
    asm("mov.u32 %0, %%cluster_ctarank;" : "=r"(rank));
    const int dir = blockIdx.x >> 3;
    const float* __restrict__ Whh = dir ? WhhB : WhhF;
    const float* __restrict__ pre = &g_pre[dir][0][0];

    const int tid  = threadIdx.x;
    const int u    = tid >> 3;          // hidden unit 0..31 within CTA
    const int sub  = tid & 7;           // also: destination CTA for the send
    const int g    = sub >> 1;          // gate 0..3 (i,f,g,o)
    const int half = sub & 1;           // column half
    const int gu   = (int)rank * 32 + u;
    const int grow = g * HH_ + gu;

    // weights into registers as packed f32x2
    unsigned long long w2[64];
    {
        const ulonglong2* wr = reinterpret_cast<const ulonglong2*>(
            Whh + (size_t)grow * HH_ + half * 128);
#pragma unroll
        for (int k = 0; k < 32; k++) {
            ulonglong2 v = wr[k];
            w2[2 * k] = v.x; w2[2 * k + 1] = v.y;
        }
    }

    // init state (all 8 threads of a unit track c redundantly & identically)
    if (tid < HH_) hbuf[0][tid] = h0[dir * HH_ + tid];
    float c = c0[dir * HH_ + gu];

    unsigned mbl[2];
    mbl[0] = (unsigned)__cvta_generic_to_shared(&mbar[0]);
    mbl[1] = (unsigned)__cvta_generic_to_shared(&mbar[1]);

    // hoisted remote addresses: this thread's destination slot in CTA 'sub'
    unsigned dstR[2], mbaR[2];
    {
        unsigned h0a = (unsigned)__cvta_generic_to_shared(&hbuf[0][0]) + ((unsigned)gu << 2);
        unsigned h1a = (unsigned)__cvta_generic_to_shared(&hbuf[1][0]) + ((unsigned)gu << 2);
        asm("mapa.shared::cluster.u32 %0, %1, %2;" : "=r"(dstR[0]) : "r"(h0a), "r"((unsigned)sub));
        asm("mapa.shared::cluster.u32 %0, %1, %2;" : "=r"(dstR[1]) : "r"(h1a), "r"((unsigned)sub));
        asm("mapa.shared::cluster.u32 %0, %1, %2;" : "=r"(mbaR[0]) : "r"(mbl[0]), "r"((unsigned)sub));
        asm("mapa.shared::cluster.u32 %0, %1, %2;" : "=r"(mbaR[1]) : "r"(mbl[1]), "r"((unsigned)sub));
    }

    if (tid == 0) {
        // arrival count = 1 (tid0's expect_tx); completion driven by 1024B of tx
        asm volatile("mbarrier.init.shared.b64 [%0], %1;" :: "r"(mbl[0]), "r"(1u) : "memory");
        asm volatile("mbarrier.init.shared.b64 [%0], %1;" :: "r"(mbl[1]), "r"(1u) : "memory");
        // pre-arm both barriers for their first uses (steps 1 and 2)
        asm volatile("mbarrier.arrive.expect_tx.shared.b64 _, [%0], %1;"
                     :: "r"(mbl[1]), "r"(1024u) : "memory");
        asm volatile("mbarrier.arrive.expect_tx.shared.b64 _, [%0], %1;"
                     :: "r"(mbl[0]), "r"(1024u) : "memory");
    }
    __syncthreads();
    cluster_sync_();   // barrier init/arming + hbuf[0] visible cluster-wide

    int phase0 = 0, phase1 = 0;
    const float gmul = (g == 2) ? 2.f : 1.f;   // tanh(x) = 2*sigm(2x)-1
    const int b0 = g & 1, b1 = g >> 1;

    // software prefetch of the input projection, 1 step ahead
    float prevN = pre[(size_t)(dir ? (TT_ - 1) : 0) * GG_ + grow];

    for (int s = 0; s < TT_; s++) {
        const int tt = dir ? (TT_ - 1 - s) : s;

        const float prev = prevN;
        if (s + 1 < TT_) {
            const int tn2 = dir ? (TT_ - 2 - s) : (s + 1);
            prevN = pre[(size_t)tn2 * GG_ + grow];   // issued early, consumed next step
        }

        const ulonglong2* h2 = reinterpret_cast<const ulonglong2*>(&hbuf[s & 1][half << 7]);
        unsigned long long a0 = 0ull, a1 = 0ull;
#pragma unroll
        for (int k = 0; k < 32; k++) {
            ulonglong2 hv = h2[k];
            a0 = ffma2_(w2[2 * k],     hv.x, a0);
            a1 = ffma2_(w2[2 * k + 1], hv.y, a1);
        }
        float2 p0 = unpack2_(a0), p1 = unpack2_(a1);
        float val = (p0.x + p0.y) + (p1.x + p1.y);
        if (!half) val += prev;
        val += __shfl_xor_sync(0xffffffffu, val, 1);   // full gate pre-activation (both halves)

        // own-gate nonlinearity
        float sg = sigm_(val * gmul);
        float A = (g == 2) ? (2.f * sg - 1.f) : sg;    // act of gate g

        // butterfly exchange: collect all 4 gate activations on all 8 threads
        float B = __shfl_xor_sync(0xffffffffu, A, 2);  // gate g^1
        float C = __shfl_xor_sync(0xffffffffu, A, 4);  // gate g^2
        float D = __shfl_xor_sync(0xffffffffu, B, 4);  // gate g^3
        // gate j = arr[j ^ g], arr = {A,B,C,D}
        float gi = b1 ? (b0 ? D : C) : (b0 ? B : A);   // gate 0 (i)
        float gf = b1 ? (b0 ? C : D) : (b0 ? A : B);   // gate 1 (f)
        float gg = b1 ? (b0 ? B : A) : (b0 ? D : C);   // gate 2 (g)
        float go = b1 ? (b0 ? A : B) : (b0 ? C : D);   // gate 3 (o)

        c = gf * c + gi * gg;
        float h = go * tanh_(c);

        if (s + 1 < TT_) {
            const int nb = (s + 1) & 1;
            // single-transaction remote store + destination-barrier tx update
            asm volatile(
                "st.async.shared::cluster.mbarrier::complete_tx::bytes.u32 [%0], %1, [%2];"
                :: "r"(dstR[nb]), "r"(__float_as_uint(h)), "r"(mbaR[nb]) : "memory");
        }

        if (sub == 0) g_h[tt][dir * HH_ + gu] = h;   // off critical path

        if (s + 1 < TT_) {
            if ((s + 1) & 1) {
                mbar_wait_cluster_(mbl[1], (unsigned)(phase1 & 1)); phase1++;
                if (tid == 0)   // re-arm for this barrier's next use (step s+3)
                    asm volatile("mbarrier.arrive.expect_tx.shared.b64 _, [%0], %1;"
                                 :: "r"(mbl[1]), "r"(1024u) : "memory");
            } else {
                mbar_wait_cluster_(mbl[0], (unsigned)(phase0 & 1)); phase0++;
                if (tid == 0)
                    asm volatile("mbarrier.arrive.expect_tx.shared.b64 _, [%0], %1;"
                                 :: "r"(mbl[0]), "r"(1024u) : "memory");
            }
        }
    }
    cluster_sync_();   // safe teardown
}

// =====================================================================
// Phase 3: feats[t][j] = h[t] . W_out[j] + b_out[j]   (32 t-rows/block)
// =====================================================================
__global__ void __launch_bounds__(256) feats_kernel(
    const float* __restrict__ Wout, const float* __restrict__ bout)
{
    extern __shared__ float sm[];
    float* Ws = sm;                 // [32][513] padded
    float* hs = sm + KK_ * 513;     // [32][512]
    const int t0 = blockIdx.x * 32;
    const int tid = threadIdx.x;

    for (int i = tid; i < KK_ * HC_; i += 256) {
        int j = i >> 9, k = i & 511;
        Ws[j * 513 + k] = Wout[i];
    }
    const float* hflat = &g_h[t0][0];
    for (int i = tid; i < 32 * HC_; i += 256) hs[i] = hflat[i];
    __syncthreads();

    const int j = tid & 31;
    const int r0 = tid >> 5;
    const float bj = bout[j];
    for (int r = r0; r < 32; r += 8) {
        const float* hr = hs + r * HC_;
        const float* wr = Ws + j * 513;
        float s0 = 0.f, s1 = 0.f, s2 = 0.f, s3 = 0.f;
#pragma unroll 4
        for (int k = 0; k < HC_; k += 4) {
            s0 = fmaf(hr[k + 0], wr[k + 0], s0);
            s1 = fmaf(hr[k + 1], wr[k + 1], s1);
            s2 = fmaf(hr[k + 2], wr[k + 2], s2);
            s3 = fmaf(hr[k + 3], wr[k + 3], s3);
        }
        g_feats[t0 + r][j] = (s0 + s1) + (s2 + s3) + bj;
    }
}

// =====================================================================
// Phase 4: Viterbi. One block, 1024 threads: warp = tag j, lane = prev tag i.
// =====================================================================
#define VCHUNK 256

__global__ void __launch_bounds__(1024) viterbi_kernel(
    const float* __restrict__ trans, float* __restrict__ out, int out_size)
{
    extern __shared__ float smv[];
    float* transS = smv;                         // [32][32] transS[j][i] = trans[i][j]
    float* alpha  = transS + 1024;               // [2][32]
    float* fbuf   = alpha + 64;                  // [VCHUNK][32]
    unsigned char* ixs = (unsigned char*)(fbuf + VCHUNK * 32);  // [T-1][32]

    const int tid = threadIdx.x;
    const int i = tid & 31;     // previous tag (lane)
    const int j = tid >> 5;     // current tag (warp)

    transS[j * 32 + i] = trans[i * 32 + j];
    if (tid < 32) alpha[tid] = g_feats[0][tid];
    __syncthreads();
    const float tr = transS[j * 32 + i];
    const float* fflat = &g_feats[0][0];

    int p = 0;
    for (int t = 1; t < TT_; t++) {
        const int ci = (t - 1) & (VCHUNK - 1);
        if (ci == 0) {
            __syncthreads();
            const int base2 = t * 32;
            for (int u = tid; u < VCHUNK * 32 && base2 + u < TT_ * 32; u += 1024)
                fbuf[u] = fflat[base2 + u];
            __syncthreads();
        }
        float s = alpha[p * 32 + i] + tr;
        unsigned uu = __float_as_uint(s);
        uu = (uu & 0x80000000u) ? ~uu : (uu | 0x80000000u);
        unsigned best = __reduce_max_sync(0xffffffffu, uu);
        unsigned m = __ballot_sync(0xffffffffu, uu == best);
        int arg = __ffs(m) - 1;                     // lowest index on ties (matches argmax)
        float bs = __shfl_sync(0xffffffffu, s, arg);
        if (i == 0) {
            alpha[(p ^ 1) * 32 + j] = bs + fbuf[ci * 32 + j];
            ixs[(t - 1) * 32 + j] = (unsigned char)arg;
        }
        __syncthreads();
        p ^= 1;
    }

    if (tid < 32) {
        float s = alpha[p * 32 + i];
        unsigned uu = __float_as_uint(s);
        uu = (uu & 0x80000000u) ? ~uu : (uu | 0x80000000u);
        unsigned best = __reduce_max_sync(0xffffffffu, uu);
        unsigned m = __ballot_sync(0xffffffffu, uu == best);
        int arg = __ffs(m) - 1;
        float score = __shfl_sync(0xffffffffu, s, arg);
        if (i == 0) {
            if (out_size > TT_) out[TT_] = score;
            int cur = arg;
            out[TT_ - 1] = (float)cur;
            for (int t = TT_ - 2; t >= 0; t--) {
                cur = ixs[t * 32 + cur];
                out[t] = (float)cur;
            }
        }
    }
}

// =====================================================================
extern "C" void kernel_launch(void* const* d_in, const int* in_sizes, int n_in,
                              void* d_out, int out_size)
{
    const int*   sent  = (const int*)  d_in[0];
    const float* embed = (const float*)d_in[1];
    const float* WihF  = (const float*)d_in[2];
    const float* WhhF  = (const float*)d_in[3];
    const float* bihF  = (const float*)d_in[4];
    const float* bhhF  = (const float*)d_in[5];
    const float* WihB  = (const float*)d_in[6];
    const float* WhhB  = (const float*)d_in[7];
    const float* bihB  = (const float*)d_in[8];
    const float* bhhB  = (const float*)d_in[9];
    const float* h0    = (const float*)d_in[10];
    const float* c0    = (const float*)d_in[11];
    const float* Wout  = (const float*)d_in[12];
    const float* bout  = (const float*)d_in[13];
    const float* trans = (const float*)d_in[14];
    float* out = (float*)d_out;

    const int feats_smem = (KK_ * 513 + 32 * HC_) * 4;                        // ~131 KB
    const int vit_smem   = (1024 + 64 + VCHUNK * 32) * 4 + (TT_ - 1) * 32;    // ~168 KB
    cudaFuncSetAttribute(feats_kernel,   cudaFuncAttributeMaxDynamicSharedMemorySize, feats_smem);
    cudaFuncSetAttribute(viterbi_kernel, cudaFuncAttributeMaxDynamicSharedMemorySize, vit_smem);

    pre_gemm_kernel<<<dim3(16, 64, 2), 256>>>(sent, embed, WihF, bihF, bhhF, WihB, bihB, bhhB);
    lstm_rec_kernel<<<16, 256>>>(WhhF, WhhB, h0, c0);
    feats_kernel<<<128, 256, feats_smem>>>(Wout, bout);
    viterbi_kernel<<<1, 1024, vit_smem>>>(trans, out, out_size);
}

// round 11
// speedup vs baseline: 1.6058x; 1.6058x over previous
#include <cuda_runtime.h>

// Problem dimensions (fixed by the reference)
#define TT_  4096   // sequence length T
#define EE_  256    // embed dim E
#define HH_  256    // per-direction hidden Hh
#define GG_  1024   // 4*Hh gate rows
#define KK_  32     // tags K
#define HC_  512    // concat hidden H

// ---------------- device scratch (no mallocs allowed) ----------------
__device__ float g_pre[2][TT_][GG_];   // input projections + biases, per direction (32 MB)
__device__ float g_h[TT_][HC_];        // concat hidden states (8 MB)
__device__ float g_feats[TT_][KK_];    // emission scores (512 KB)

// ---------------- packed fp32x2 helpers (SASS FFMA2) ----------------
__device__ __forceinline__ unsigned long long ffma2_(unsigned long long a,
                                                     unsigned long long b,
                                                     unsigned long long c) {
    unsigned long long d;
    asm("fma.rn.f32x2 %0, %1, %2, %3;" : "=l"(d) : "l"(a), "l"(b), "l"(c));
    return d;
}
__device__ __forceinline__ unsigned long long pack2_(float x) {
    unsigned long long d;
    asm("mov.b64 %0, {%1, %1};" : "=l"(d) : "f"(x));
    return d;
}
__device__ __forceinline__ float2 unpack2_(unsigned long long v) {
    float2 r;
    asm("mov.b64 {%0, %1}, %2;" : "=f"(r.x), "=f"(r.y) : "l"(v));
    return r;
}

// =====================================================================
// Phase 1: fused embedding gather + input projection GEMM (f32x2)
// =====================================================================
__global__ void __launch_bounds__(256) pre_gemm_kernel(
    const int* __restrict__ sent, const float* __restrict__ embed,
    const float* __restrict__ WihF, const float* __restrict__ bihF, const float* __restrict__ bhhF,
    const float* __restrict__ WihB, const float* __restrict__ bihB, const float* __restrict__ bhhB)
{
    const int dir = blockIdx.z;
    const float* __restrict__ Wih = dir ? WihB : WihF;
    const float* __restrict__ bih = dir ? bihB : bihF;
    const float* __restrict__ bhh = dir ? bhhB : bhhF;

    const int t0 = blockIdx.y * 64;
    const int j0 = blockIdx.x * 64;
    const int tid = threadIdx.x;

    __shared__ __align__(16) float As[32][68];
    __shared__ __align__(16) float Bs[32][68];
    __shared__ int ssent[64];

    if (tid < 64) ssent[tid] = sent[t0 + tid];
    __syncthreads();

    const int tl = tid >> 2;
    const int kq = (tid & 3) * 8;
    const int tm = tid & 15;
    const int tn = tid >> 4;

    unsigned long long acc2[4][2];
#pragma unroll
    for (int a = 0; a < 4; a++) { acc2[a][0] = 0ull; acc2[a][1] = 0ull; }

    for (int k0 = 0; k0 < EE_; k0 += 32) {
        const float4* ar = reinterpret_cast<const float4*>(embed + (size_t)ssent[tl] * EE_ + k0 + kq);
        float4 a0 = ar[0], a1 = ar[1];
        const float4* br = reinterpret_cast<const float4*>(Wih + (size_t)(j0 + tl) * EE_ + k0 + kq);
        float4 b0 = br[0], b1 = br[1];
        __syncthreads();
        As[kq + 0][tl] = a0.x; As[kq + 1][tl] = a0.y; As[kq + 2][tl] = a0.z; As[kq + 3][tl] = a0.w;
        As[kq + 4][tl] = a1.x; As[kq + 5][tl] = a1.y; As[kq + 6][tl] = a1.z; As[kq + 7][tl] = a1.w;
        Bs[kq + 0][tl] = b0.x; Bs[kq + 1][tl] = b0.y; Bs[kq + 2][tl] = b0.z; Bs[kq + 3][tl] = b0.w;
        Bs[kq + 4][tl] = b1.x; Bs[kq + 5][tl] = b1.y; Bs[kq + 6][tl] = b1.z; Bs[kq + 7][tl] = b1.w;
        __syncthreads();
#pragma unroll
        for (int kk = 0; kk < 32; kk++) {
            float4 av = *reinterpret_cast<const float4*>(&As[kk][tm * 4]);
            ulonglong2 bv = *reinterpret_cast<const ulonglong2*>(&Bs[kk][tn * 4]);
            unsigned long long sa0 = pack2_(av.x), sa1 = pack2_(av.y);
            unsigned long long sa2 = pack2_(av.z), sa3 = pack2_(av.w);
            acc2[0][0] = ffma2_(sa0, bv.x, acc2[0][0]); acc2[0][1] = ffma2_(sa0, bv.y, acc2[0][1]);
            acc2[1][0] = ffma2_(sa1, bv.x, acc2[1][0]); acc2[1][1] = ffma2_(sa1, bv.y, acc2[1][1]);
            acc2[2][0] = ffma2_(sa2, bv.x, acc2[2][0]); acc2[2][1] = ffma2_(sa2, bv.y, acc2[2][1]);
            acc2[3][0] = ffma2_(sa3, bv.x, acc2[3][0]); acc2[3][1] = ffma2_(sa3, bv.y, acc2[3][1]);
        }
    }

    float bias[4];
#pragma unroll
    for (int b = 0; b < 4; b++) bias[b] = bih[j0 + tn * 4 + b] + bhh[j0 + tn * 4 + b];

#pragma unroll
    for (int a = 0; a < 4; a++) {
        float2 p0 = unpack2_(acc2[a][0]);
        float2 p1 = unpack2_(acc2[a][1]);
        float4 v;
        v.x = p0.x + bias[0]; v.y = p0.y + bias[1];
        v.z = p1.x + bias[2]; v.w = p1.y + bias[3];
        *reinterpret_cast<float4*>(&g_pre[dir][t0 + tm * 4 + a][j0 + tn * 4]) = v;
    }
}

// ---------------- recurrence helpers ----------------
__device__ __forceinline__ float sigm_(float x) {
    return __fdividef(1.f, 1.f + __expf(-x));     // rcp.approx path
}
__device__ __forceinline__ float tanh_(float x) {
    return __fdividef(2.f, 1.f + __expf(-2.f * x)) - 1.f;
}
__device__ __forceinline__ void cluster_sync_() {
    asm volatile("barrier.cluster.arrive.aligned;" ::: "memory");
    asm volatile("barrier.cluster.wait.aligned;" ::: "memory");
}
// Wait with CTA-scope acquire: remote stores land directly in our smem banks
// (no cache in between); the cluster-release of the remote arrive pairs with
// this per the ptx_helpers cg2-multicast precedent. acquire.cluster is the
// heavyweight variant (L1-invalidate class) and is NOT needed here.
__device__ __forceinline__ void mbar_wait_(unsigned mbar, unsigned parity) {
    unsigned done;
    asm volatile(
        "{\n\t.reg .pred p;\n\t"
        "mbarrier.try_wait.parity.acquire.cta.shared::cta.b64 p, [%1], %2, 0x989680;\n\t"
        "selp.b32 %0, 1, 0, p;\n\t}"
        : "=r"(done) : "r"(mbar), "r"(parity) : "memory");
    while (!done) {
        asm volatile(
            "{\n\t.reg .pred p;\n\t"
            "mbarrier.try_wait.parity.acquire.cta.shared::cta.b64 p, [%1], %2, 0x989680;\n\t"
            "selp.b32 %0, 1, 0, p;\n\t}"
            : "=r"(done) : "r"(mbar), "r"(parity) : "memory");
    }
}

// =====================================================================
// Phase 2: BiLSTM recurrence (R7 structure). 2 clusters of 8 CTAs.
// tid = u*8 + sub, sub = g*2 + half. All 8 threads of a unit compute the
// full gate set redundantly via butterfly shfl_xor; each thread sends h to
// exactly ONE destination CTA (dest = sub) with hoisted-mapa remote store
// + remote arrive. Waits use acquire.cta (this round's single change).
// =====================================================================
__global__ void __cluster_dims__(8, 1, 1) __launch_bounds__(256, 1) lstm_rec_kernel(
    const float* __restrict__ WhhF, const float* __restrict__ WhhB,
    const float* __restrict__ h0, const float* __restrict__ c0)
{
    __shared__ __align__(16) float hbuf[2][HH_];     // assembled h (all 8 chunks)
    __shared__ __align__(8) unsigned long long mbar[2];

    unsigned rank;
    asm("mov.u32 %0, %%cluster_ctarank;" : "=r"(rank));
    const int dir = blockIdx.x >> 3;
    const float* __restrict__ Whh = dir ? WhhB : WhhF;
    const float* __restrict__ pre = &g_pre[dir][0][0];

    const int tid  = threadIdx.x;
    const int u    = tid >> 3;          // hidden unit 0..31 within CTA
    const int sub  = tid & 7;           // also: destination CTA for the send
    const int g    = sub >> 1;          // gate 0..3 (i,f,g,o)
    const int half = sub & 1;           // column half
    const int gu   = (int)rank * 32 + u;
    const int grow = g * HH_ + gu;

    // weights into registers as packed f32x2
    unsigned long long w2[64];
    {
        const ulonglong2* wr = reinterpret_cast<const ulonglong2*>(
            Whh + (size_t)grow * HH_ + half * 128);
#pragma unroll
        for (int k = 0; k < 32; k++) {
            ulonglong2 v = wr[k];
            w2[2 * k] = v.x; w2[2 * k + 1] = v.y;
        }
    }

    // init state (all 8 threads of a unit track c redundantly & identically)
    if (tid < HH_) hbuf[0][tid] = h0[dir * HH_ + tid];
    float c = c0[dir * HH_ + gu];

    unsigned mbl[2];
    mbl[0] = (unsigned)__cvta_generic_to_shared(&mbar[0]);
    mbl[1] = (unsigned)__cvta_generic_to_shared(&mbar[1]);

    // hoisted remote addresses: this thread's destination slot in CTA 'sub'
    unsigned dstR[2], mbaR[2];
    {
        unsigned h0a = (unsigned)__cvta_generic_to_shared(&hbuf[0][0]) + ((unsigned)gu << 2);
        unsigned h1a = (unsigned)__cvta_generic_to_shared(&hbuf[1][0]) + ((unsigned)gu << 2);
        asm("mapa.shared::cluster.u32 %0, %1, %2;" : "=r"(dstR[0]) : "r"(h0a), "r"((unsigned)sub));
        asm("mapa.shared::cluster.u32 %0, %1, %2;" : "=r"(dstR[1]) : "r"(h1a), "r"((unsigned)sub));
        asm("mapa.shared::cluster.u32 %0, %1, %2;" : "=r"(mbaR[0]) : "r"(mbl[0]), "r"((unsigned)sub));
        asm("mapa.shared::cluster.u32 %0, %1, %2;" : "=r"(mbaR[1]) : "r"(mbl[1]), "r"((unsigned)sub));
    }

    if (tid == 0) {
        // 256 arrives per phase: 32 units x 8 source CTAs
        asm volatile("mbarrier.init.shared.b64 [%0], %1;" :: "r"(mbl[0]), "r"(256u) : "memory");
        asm volatile("mbarrier.init.shared.b64 [%0], %1;" :: "r"(mbl[1]), "r"(256u) : "memory");
    }
    __syncthreads();
    cluster_sync_();   // mbarrier init + hbuf[0] visible cluster-wide

    int phase0 = 0, phase1 = 0;
    const float gmul = (g == 2) ? 2.f : 1.f;   // tanh(x) = 2*sigm(2x)-1
    const int b0 = g & 1, b1 = g >> 1;

    // software prefetch of the input projection, 1 step ahead
    float prevN = pre[(size_t)(dir ? (TT_ - 1) : 0) * GG_ + grow];

    for (int s = 0; s < TT_; s++) {
        const int tt = dir ? (TT_ - 1 - s) : s;

        const float prev = prevN;
        if (s + 1 < TT_) {
            const int tn2 = dir ? (TT_ - 2 - s) : (s + 1);
            prevN = pre[(size_t)tn2 * GG_ + grow];   // issued early, consumed next step
        }

        const ulonglong2* h2 = reinterpret_cast<const ulonglong2*>(&hbuf[s & 1][half << 7]);
        unsigned long long a0 = 0ull, a1 = 0ull;
#pragma unroll
        for (int k = 0; k < 32; k++) {
            ulonglong2 hv = h2[k];
            a0 = ffma2_(w2[2 * k],     hv.x, a0);
            a1 = ffma2_(w2[2 * k + 1], hv.y, a1);
        }
        float2 p0 = unpack2_(a0), p1 = unpack2_(a1);
        float val = (p0.x + p0.y) + (p1.x + p1.y);
        if (!half) val += prev;
        val += __shfl_xor_sync(0xffffffffu, val, 1);   // full gate pre-activation (both halves)

        // own-gate nonlinearity
        float sg = sigm_(val * gmul);
        float A = (g == 2) ? (2.f * sg - 1.f) : sg;    // act of gate g

        // butterfly exchange: collect all 4 gate activations on all 8 threads
        float B = __shfl_xor_sync(0xffffffffu, A, 2);  // gate g^1
        float C = __shfl_xor_sync(0xffffffffu, A, 4);  // gate g^2
        float D = __shfl_xor_sync(0xffffffffu, B, 4);  // gate g^3
        // gate j = arr[j ^ g], arr = {A,B,C,D}
        float gi = b1 ? (b0 ? D : C) : (b0 ? B : A);   // gate 0 (i)
        float gf = b1 ? (b0 ? C : D) : (b0 ? A : B);   // gate 1 (f)
        float gg = b1 ? (b0 ? B : A) : (b0 ? D : C);   // gate 2 (g)
        float go = b1 ? (b0 ? A : B) : (b0 ? C : D);   // gate 3 (o)

        c = gf * c + gi * gg;
        float h = go * tanh_(c);

        if (s + 1 < TT_) {
            const int nb = (s + 1) & 1;
            // one remote store + one remote arrive per thread (dest = sub)
            asm volatile("st.shared::cluster.f32 [%0], %1;"
                         :: "r"(dstR[nb]), "f"(h) : "memory");
            asm volatile("mbarrier.arrive.shared::cluster.b64 _, [%0];"
                         :: "r"(mbaR[nb]) : "memory");
        }

        if (sub == 0) g_h[tt][dir * HH_ + gu] = h;   // off critical path

        if (s + 1 < TT_) {
            if ((s + 1) & 1) { mbar_wait_(mbl[1], (unsigned)(phase1 & 1)); phase1++; }
            else             { mbar_wait_(mbl[0], (unsigned)(phase0 & 1)); phase0++; }
        }
    }
    cluster_sync_();   // safe teardown
}

// =====================================================================
// Phase 3: feats[t][j] = h[t] . W_out[j] + b_out[j]   (32 t-rows/block)
// =====================================================================
__global__ void __launch_bounds__(256) feats_kernel(
    const float* __restrict__ Wout, const float* __restrict__ bout)
{
    extern __shared__ float sm[];
    float* Ws = sm;                 // [32][513] padded
    float* hs = sm + KK_ * 513;     // [32][512]
    const int t0 = blockIdx.x * 32;
    const int tid = threadIdx.x;

    for (int i = tid; i < KK_ * HC_; i += 256) {
        int j = i >> 9, k = i & 511;
        Ws[j * 513 + k] = Wout[i];
    }
    const float* hflat = &g_h[t0][0];
    for (int i = tid; i < 32 * HC_; i += 256) hs[i] = hflat[i];
    __syncthreads();

    const int j = tid & 31;
    const int r0 = tid >> 5;
    const float bj = bout[j];
    for (int r = r0; r < 32; r += 8) {
        const float* hr = hs + r * HC_;
        const float* wr = Ws + j * 513;
        float s0 = 0.f, s1 = 0.f, s2 = 0.f, s3 = 0.f;
#pragma unroll 4
        for (int k = 0; k < HC_; k += 4) {
            s0 = fmaf(hr[k + 0], wr[k + 0], s0);
            s1 = fmaf(hr[k + 1], wr[k + 1], s1);
            s2 = fmaf(hr[k + 2], wr[k + 2], s2);
            s3 = fmaf(hr[k + 3], wr[k + 3], s3);
        }
        g_feats[t0 + r][j] = (s0 + s1) + (s2 + s3) + bj;
    }
}

// =====================================================================
// Phase 4: Viterbi. One block, 1024 threads: warp = tag j, lane = prev tag i.
// =====================================================================
#define VCHUNK 256

__global__ void __launch_bounds__(1024) viterbi_kernel(
    const float* __restrict__ trans, float* __restrict__ out, int out_size)
{
    extern __shared__ float smv[];
    float* transS = smv;                         // [32][32] transS[j][i] = trans[i][j]
    float* alpha  = transS + 1024;               // [2][32]
    float* fbuf   = alpha + 64;                  // [VCHUNK][32]
    unsigned char* ixs = (unsigned char*)(fbuf + VCHUNK * 32);  // [T-1][32]

    const int tid = threadIdx.x;
    const int i = tid & 31;     // previous tag (lane)
    const int j = tid >> 5;     // current tag (warp)

    transS[j * 32 + i] = trans[i * 32 + j];
    if (tid < 32) alpha[tid] = g_feats[0][tid];
    __syncthreads();
    const float tr = transS[j * 32 + i];
    const float* fflat = &g_feats[0][0];

    int p = 0;
    for (int t = 1; t < TT_; t++) {
        const int ci = (t - 1) & (VCHUNK - 1);
        if (ci == 0) {
            __syncthreads();
            const int base2 = t * 32;
            for (int u = tid; u < VCHUNK * 32 && base2 + u < TT_ * 32; u += 1024)
                fbuf[u] = fflat[base2 + u];
            __syncthreads();
        }
        float s = alpha[p * 32 + i] + tr;
        unsigned uu = __float_as_uint(s);
        uu = (uu & 0x80000000u) ? ~uu : (uu | 0x80000000u);
        unsigned best = __reduce_max_sync(0xffffffffu, uu);
        unsigned m = __ballot_sync(0xffffffffu, uu == best);
        int arg = __ffs(m) - 1;                     // lowest index on ties (matches argmax)
        float bs = __shfl_sync(0xffffffffu, s, arg);
        if (i == 0) {
            alpha[(p ^ 1) * 32 + j] = bs + fbuf[ci * 32 + j];
            ixs[(t - 1) * 32 + j] = (unsigned char)arg;
        }
        __syncthreads();
        p ^= 1;
    }

    if (tid < 32) {
        float s = alpha[p * 32 + i];
        unsigned uu = __float_as_uint(s);
        uu = (uu & 0x80000000u) ? ~uu : (uu | 0x80000000u);
        unsigned best = __reduce_max_sync(0xffffffffu, uu);
        unsigned m = __ballot_sync(0xffffffffu, uu == best);
        int arg = __ffs(m) - 1;
        float score = __shfl_sync(0xffffffffu, s, arg);
        if (i == 0) {
            if (out_size > TT_) out[TT_] = score;
            int cur = arg;
            out[TT_ - 1] = (float)cur;
            for (int t = TT_ - 2; t >= 0; t--) {
                cur = ixs[t * 32 + cur];
                out[t] = (float)cur;
            }
        }
    }
}

// =====================================================================
extern "C" void kernel_launch(void* const* d_in, const int* in_sizes, int n_in,
                              void* d_out, int out_size)
{
    const int*   sent  = (const int*)  d_in[0];
    const float* embed = (const float*)d_in[1];
    const float* WihF  = (const float*)d_in[2];
    const float* WhhF  = (const float*)d_in[3];
    const float* bihF  = (const float*)d_in[4];
    const float* bhhF  = (const float*)d_in[5];
    const float* WihB  = (const float*)d_in[6];
    const float* WhhB  = (const float*)d_in[7];
    const float* bihB  = (const float*)d_in[8];
    const float* bhhB  = (const float*)d_in[9];
    const float* h0    = (const float*)d_in[10];
    const float* c0    = (const float*)d_in[11];
    const float* Wout  = (const float*)d_in[12];
    const float* bout  = (const float*)d_in[13];
    const float* trans = (const float*)d_in[14];
    float* out = (float*)d_out;

    const int feats_smem = (KK_ * 513 + 32 * HC_) * 4;                        // ~131 KB
    const int vit_smem   = (1024 + 64 + VCHUNK * 32) * 4 + (TT_ - 1) * 32;    // ~168 KB
    cudaFuncSetAttribute(feats_kernel,   cudaFuncAttributeMaxDynamicSharedMemorySize, feats_smem);
    cudaFuncSetAttribute(viterbi_kernel, cudaFuncAttributeMaxDynamicSharedMemorySize, vit_smem);

    pre_gemm_kernel<<<dim3(16, 64, 2), 256>>>(sent, embed, WihF, bihF, bhhF, WihB, bihB, bhhB);
    lstm_rec_kernel<<<16, 256>>>(WhhF, WhhB, h0, c0);
    feats_kernel<<<128, 256, feats_smem>>>(Wout, bout);
    viterbi_kernel<<<1, 1024, vit_smem>>>(trans, out, out_size);
}